// round 10
// baseline (speedup 1.0000x reference)
#include <cuda_runtime.h>
#include <cuda_bf16.h>
#include <cstdint>
#include <cstddef>

#define N_PTS 32768
#define HID   256
#define KTEST 1024
#define PI_F  3.14159274101257324f

// ---------------- global scratch ----------------
__device__ __nv_bfloat16 g_jetA[(size_t)N_PTS * 3 * 2 * HID];
__device__ __nv_bfloat16 g_jetB[(size_t)N_PTS * 3 * 2 * HID];
__device__ float g_part[(size_t)N_PTS * 16];
__device__ float g_r[N_PTS];
__device__ float g_Sp[8 * KTEST];
__device__ float g_ub[2];

// ---------------- math helpers ----------------
__device__ __forceinline__ float frcp(float x) {
    float r;
    asm("rcp.approx.f32 %0, %1;" : "=f"(r) : "f"(x));
    return r;
}

__device__ __forceinline__ void tanh4(const float* z, float* h) {
    float e[4], ep[4];
#pragma unroll
    for (int i = 0; i < 4; i++) {
        float zc = fminf(fmaxf(z[i], -9.0f), 9.0f);
        e[i]  = __expf(2.0f * zc);
        ep[i] = e[i] + 1.0f;
    }
    float p01   = ep[0] * ep[1];
    float p012  = p01 * ep[2];
    float p0123 = p012 * ep[3];
    float r = frcp(p0123);
    float i3 = p012 * r;  r *= ep[3];
    float i2 = p01  * r;  r *= ep[2];
    float i1 = ep[0] * r; r *= ep[1];
    float i0 = r;
    h[0] = (e[0] - 1.0f) * i0;
    h[1] = (e[1] - 1.0f) * i1;
    h[2] = (e[2] - 1.0f) * i2;
    h[3] = (e[3] - 1.0f) * i3;
}

__device__ __forceinline__ float my_sin(float a) {
    const float INV_PI = 0.3183098861837907f;
    float n = rintf(a * INV_PI);
    float r = fmaf(n, -3.14159274101257324f, a);
    r = fmaf(n, 8.742277657347586e-8f, r);
    float s2 = r * r;
    float p = -2.50521084e-8f;
    p = fmaf(p, s2, 2.75573192e-6f);
    p = fmaf(p, s2, -1.98412698e-4f);
    p = fmaf(p, s2, 8.33333333e-3f);
    p = fmaf(p, s2, -1.66666667e-1f);
    float s = fmaf(p * s2, r, r);
    return (((int)n) & 1) ? -s : s;
}

__device__ __forceinline__ void bsplit(float v, __nv_bfloat16& hi, __nv_bfloat16& lo) {
    hi = __float2bfloat16(v);
    lo = __float2bfloat16(v - __bfloat162float(hi));
}

// bf16 HMMA (sm_80+ PTX).
__device__ __forceinline__ void mma16816(float* d, const uint32_t* a, const uint32_t* b) {
    asm volatile(
        "mma.sync.aligned.m16n8k16.row.col.f32.bf16.bf16.f32 "
        "{%0,%1,%2,%3}, {%4,%5,%6,%7}, {%8,%9}, {%0,%1,%2,%3};"
        : "+f"(d[0]), "+f"(d[1]), "+f"(d[2]), "+f"(d[3])
        : "r"(a[0]), "r"(a[1]), "r"(a[2]), "r"(a[3]), "r"(b[0]), "r"(b[1]));
}

// ldmatrix x4 (sm_75+ PTX).
__device__ __forceinline__ void ldsm4(uint32_t* r, uint32_t addr) {
    asm volatile("ldmatrix.sync.aligned.m8n8.x4.shared.b16 {%0,%1,%2,%3}, [%4];"
        : "=r"(r[0]), "=r"(r[1]), "=r"(r[2]), "=r"(r[3]) : "r"(addr));
}

__device__ __forceinline__ uint32_t smem_u32(const void* p) {
    uint32_t a;
    asm("{ .reg .u64 t; cvta.to.shared.u64 t, %1; cvt.u32.u64 %0, t; }" : "=r"(a) : "l"(p));
    return a;
}

// ---------------- SMEM geometry (bf16 elements) ----------------
// B: one K=128 half for n=128 rows, restaged once: 128 x 136 stride, hi+lo.
#define SB_E    136
#define BLO_E   (128 * 136)           // 17408
#define AB_E    (2 * 17408)           // 34816 : A ring start
// A: K=32 chunk tiles, 128 rows x 32 el, XOR-granule swizzle, 6 tiles/chunk.
#define TILE_E  4096                  // 128*32
#define ABUF_E  (6 * TILE_E)          // 24576 el = 49152 B per ring slot
#define NBUF    3
#define SMEM_TOT ((AB_E + NBUF * ABUF_E) * 2)   // 217088 B (single CTA)

#define NTHREADS 512

// ---------------- MMA compute for one K=32 chunk ----------------
__device__ __forceinline__ void compute_chunk(
    uint32_t smb, int slot, int khalf,
    int wm, int wn, int lane, float acc[3][2][4][4])
{
    const int t  = lane >> 3, ri = lane & 7;
    const uint32_t aBase = AB_E + slot * ABUF_E;

#pragma unroll
    for (int ks = 0; ks < 2; ks++) {
        // B fragments: one x4 per nf -> {bh0, bh1, bl0, bl1}
        uint32_t bh[4][2], bl[4][2];
#pragma unroll
        for (int nf = 0; nf < 4; nf++) {
            int n = wn * 32 + nf * 8 + ri;
            uint32_t el = ((t >> 1) ? BLO_E : 0) + n * SB_E + khalf + ks * 16 + (t & 1) * 8;
            uint32_t rg[4];
            ldsm4(rg, smb + el * 2);
            bh[nf][0] = rg[0]; bh[nf][1] = rg[1];
            bl[nf][0] = rg[2]; bl[nf][1] = rg[3];
        }
#pragma unroll
        for (int ch = 0; ch < 3; ch++) {
            uint32_t ah[2][4], al[2][4];
#pragma unroll
            for (int mf = 0; mf < 2; mf++) {
                int rr = wm * 32 + mf * 16 + (t & 1) * 8 + ri;
                int s  = 2 * ks + (t >> 1);
                uint32_t sw = (uint32_t)((s ^ ((rr >> 1) & 3)) << 3);
                uint32_t eh = aBase + (ch * 2 + 0) * TILE_E + rr * 32 + sw;
                uint32_t el2 = aBase + (ch * 2 + 1) * TILE_E + rr * 32 + sw;
                ldsm4(ah[mf], smb + eh * 2);
                ldsm4(al[mf], smb + el2 * 2);
            }
#pragma unroll
            for (int mf = 0; mf < 2; mf++)
#pragma unroll
                for (int nf = 0; nf < 4; nf++) {
                    mma16816(acc[ch][mf][nf], ah[mf], bh[nf]);  // hi*hi
                    mma16816(acc[ch][mf][nf], ah[mf], bl[nf]);  // hi*lo
                    mma16816(acc[ch][mf][nf], al[mf], bh[nf]);  // lo*hi
                }
        }
    }
}

// cp.async prefetch of one K=32 A-chunk (48 KB) into ring slot c%3 (swizzled).
__device__ __forceinline__ void issue_chunk(uint32_t smb, const __nv_bfloat16* jin,
                                            int m0, int c, int tid) {
    const int kc = c * 32;
    const uint32_t dbase = smb + (uint32_t)(AB_E + (c % NBUF) * ABUF_E) * 2;
#pragma unroll
    for (int it = 0; it < 6; it++) {
        int seg = tid + it * NTHREADS;
        int t = seg >> 9, rem = seg & 511;
        int r = rem >> 2, s = rem & 3;
        const __nv_bfloat16* src = jin
            + (((size_t)((m0 + r) * 3 + (t >> 1)) * 2 + (t & 1)) << 8) + kc + s * 8;
        uint32_t sw = (uint32_t)((s ^ ((r >> 1) & 3)) << 3);
        uint32_t dst = dbase + (uint32_t)(t * TILE_E + r * 32 + sw) * 2;
        unsigned long long gsrc = (unsigned long long)__cvta_generic_to_global(src);
        asm volatile("cp.async.cg.shared.global [%0], [%1], 16;" :: "r"(dst), "l"(gsrc) : "memory");
    }
    asm volatile("cp.async.commit_group;" ::: "memory");
}

// Stage one K=128 half of B = W^T for n=128 cols (hi/lo split).
__device__ __forceinline__ void stage_B(__nv_bfloat16* sm, const float* __restrict__ W,
                                        int n0, int k0, int tid) {
#pragma unroll
    for (int it = 0; it < 8; it++) {
        int e = tid + it * NTHREADS;
        int k = e >> 5, n4 = e & 31;
        float4 v = *(const float4*)(W + (size_t)(k0 + k) * HID + n0 + n4 * 4);
        float vv[4] = {v.x, v.y, v.z, v.w};
#pragma unroll
        for (int u = 0; u < 4; u++) {
            __nv_bfloat16 hh, ll; bsplit(vv[u], hh, ll);
            int off = (n4 * 4 + u) * SB_E + k;
            sm[off]         = hh;
            sm[BLO_E + off] = ll;
        }
    }
}

// ---------------- layer-0 jet init ----------------
__global__ __launch_bounds__(256) void k_init(const float* __restrict__ x,
                                              const float* __restrict__ W0,
                                              const float* __restrict__ b0) {
    int gid = blockIdx.x * 256 + threadIdx.x;
    int m  = gid >> 6;
    int k  = (gid & 63) << 2;
    float xm = __ldg(x + m);
    float z[4], w[4], h[4];
#pragma unroll
    for (int u = 0; u < 4; u++) {
        w[u] = __ldg(W0 + k + u);
        z[u] = fmaf(xm, w[u], __ldg(b0 + k + u));
    }
    tanh4(z, h);
    __nv_bfloat16 st[3][2][4];
#pragma unroll
    for (int u = 0; u < 4; u++) {
        float g  = fmaf(-h[u], h[u], 1.0f);
        float d  = g * w[u];
        float e2 = -2.0f * h[u] * g * w[u] * w[u];
        bsplit(h[u], st[0][0][u], st[0][1][u]);
        bsplit(d,    st[1][0][u], st[1][1][u]);
        bsplit(e2,   st[2][0][u], st[2][1][u]);
    }
#pragma unroll
    for (int ch = 0; ch < 3; ch++)
#pragma unroll
        for (int hl = 0; hl < 2; hl++)
            *(uint2*)(g_jetA + (((size_t)(m * 3 + ch) * 2 + hl) << 8) + k)
                = *(uint2*)st[ch][hl];
}

// ---------------- fused hidden layer (512 thr, 1 CTA/SM, tile 128x128) ----------------
template<int WRITE_JET>
__global__ __launch_bounds__(NTHREADS, 1) void k_layer(
    const __nv_bfloat16* __restrict__ jin, __nv_bfloat16* __restrict__ jout,
    const float* __restrict__ W, const float* __restrict__ bias,
    const float* __restrict__ W3)
{
    extern __shared__ __nv_bfloat16 sm[];
    const int tid = threadIdx.x, lane = tid & 31, wid = tid >> 5;
    const int wm = wid & 3, wn = wid >> 2;
    const int lg = lane >> 2, lq = lane & 3;
    const int nt = blockIdx.x & 1, mt = blockIdx.x >> 1;
    const int m0 = mt * 128, n0 = nt * 128;

    const uint32_t smb = smem_u32(sm);
    issue_chunk(smb, jin, m0, 0, tid);
    issue_chunk(smb, jin, m0, 1, tid);
    stage_B(sm, W, n0, 0, tid);

    float acc[3][2][4][4];
#pragma unroll
    for (int ch = 0; ch < 3; ch++)
#pragma unroll
        for (int mf = 0; mf < 2; mf++)
#pragma unroll
            for (int nf = 0; nf < 4; nf++)
#pragma unroll
                for (int rr = 0; rr < 4; rr++) acc[ch][mf][nf][rr] = 0.f;

    // ---- 8 chunks of K=32, 3-deep cp.async ring, B restaged at c=4 ----
    for (int c = 0; c < 8; c++) {
        if (c < 7) { asm volatile("cp.async.wait_group 1;" ::: "memory"); }
        else       { asm volatile("cp.async.wait_group 0;" ::: "memory"); }
        __syncthreads();   // chunk c visible to all warps; compute c-1 done
        if (c == 4) {      // swap B to K half [128,256)
            stage_B(sm, W, n0, 128, tid);
            __syncthreads();
        }
        if (c + 2 < 8) issue_chunk(smb, jin, m0, c + 2, tid);
        compute_chunk(smb, c % NBUF, (c & 3) * 32, wm, wn, lane, acc);
    }

    // ---- epilogue ----
    if (WRITE_JET) {
#pragma unroll
        for (int mf = 0; mf < 2; mf++)
#pragma unroll
            for (int rh = 0; rh < 2; rh++) {
                const int row = m0 + wm * 32 + mf * 16 + rh * 8 + lg;
                float zz[8], aa[8], cc[8], hh[8];
#pragma unroll
                for (int nf = 0; nf < 4; nf++)
#pragma unroll
                    for (int u = 0; u < 2; u++) {
                        const int e = nf * 2 + u;
                        const int col = n0 + wn * 32 + nf * 8 + lq * 2 + u;
                        zz[e] = acc[0][mf][nf][rh * 2 + u] + __ldg(bias + col);
                        aa[e] = acc[1][mf][nf][rh * 2 + u];
                        cc[e] = acc[2][mf][nf][rh * 2 + u];
                    }
                tanh4(zz, hh);
                tanh4(zz + 4, hh + 4);
#pragma unroll
                for (int nf = 0; nf < 4; nf++) {
                    const int col = n0 + wn * 32 + nf * 8 + lq * 2;
                    const int e0 = nf * 2, e1 = nf * 2 + 1;
                    float h0 = hh[e0], h1 = hh[e1];
                    float g0 = fmaf(-h0, h0, 1.0f), g1 = fmaf(-h1, h1, 1.0f);
                    float d0 = g0 * aa[e0], d1 = g1 * aa[e1];
                    float ev0 = g0 * fmaf(-2.0f * h0 * aa[e0], aa[e0], cc[e0]);
                    float ev1 = g1 * fmaf(-2.0f * h1 * aa[e1], aa[e1], cc[e1]);
                    float vs[3][2] = {{h0, h1}, {d0, d1}, {ev0, ev1}};
#pragma unroll
                    for (int ch = 0; ch < 3; ch++) {
                        __nv_bfloat16 hA, lA, hB, lB;
                        bsplit(vs[ch][0], hA, lA);
                        bsplit(vs[ch][1], hB, lB);
                        __nv_bfloat162 hp = __halves2bfloat162(hA, hB);
                        __nv_bfloat162 lp = __halves2bfloat162(lA, lB);
                        *(uint32_t*)(jout + (((size_t)(row * 3 + ch) * 2 + 0) << 8) + col) = *(uint32_t*)&hp;
                        *(uint32_t*)(jout + (((size_t)(row * 3 + ch) * 2 + 1) << 8) + col) = *(uint32_t*)&lp;
                    }
                }
            }
    } else {
        float su[2][2] = {{0.f, 0.f}, {0.f, 0.f}};
        float se[2][2] = {{0.f, 0.f}, {0.f, 0.f}};
#pragma unroll
        for (int mf = 0; mf < 2; mf++)
#pragma unroll
            for (int rh = 0; rh < 2; rh++) {
                float zz[8], aa[8], cc[8], hh[8];
#pragma unroll
                for (int nf = 0; nf < 4; nf++)
#pragma unroll
                    for (int u = 0; u < 2; u++) {
                        const int e = nf * 2 + u;
                        const int col = n0 + wn * 32 + nf * 8 + lq * 2 + u;
                        zz[e] = acc[0][mf][nf][rh * 2 + u] + __ldg(bias + col);
                        aa[e] = acc[1][mf][nf][rh * 2 + u];
                        cc[e] = acc[2][mf][nf][rh * 2 + u];
                    }
                tanh4(zz, hh);
                tanh4(zz + 4, hh + 4);
#pragma unroll
                for (int nf = 0; nf < 4; nf++) {
                    const int col = n0 + wn * 32 + nf * 8 + lq * 2;
                    const int e0 = nf * 2, e1 = nf * 2 + 1;
                    float h0 = hh[e0], h1 = hh[e1];
                    float g0 = fmaf(-h0, h0, 1.0f), g1 = fmaf(-h1, h1, 1.0f);
                    float ev0 = g0 * fmaf(-2.0f * h0 * aa[e0], aa[e0], cc[e0]);
                    float ev1 = g1 * fmaf(-2.0f * h1 * aa[e1], aa[e1], cc[e1]);
                    float w30 = __ldg(W3 + col), w31 = __ldg(W3 + col + 1);
                    su[mf][rh] = fmaf(h0, w30, fmaf(h1, w31, su[mf][rh]));
                    se[mf][rh] = fmaf(ev0, w30, fmaf(ev1, w31, se[mf][rh]));
                }
            }
#pragma unroll
        for (int mf = 0; mf < 2; mf++)
#pragma unroll
            for (int rh = 0; rh < 2; rh++) {
                float s = su[mf][rh];
                s += __shfl_xor_sync(0xffffffffu, s, 1);
                s += __shfl_xor_sync(0xffffffffu, s, 2);
                float t = se[mf][rh];
                t += __shfl_xor_sync(0xffffffffu, t, 1);
                t += __shfl_xor_sync(0xffffffffu, t, 2);
                if (lq == 0) {
                    const int row = m0 + wm * 32 + mf * 16 + rh * 8 + lg;
                    const int p = nt * 4 + wn;
                    g_part[(size_t)row * 16 + p]     = s;
                    g_part[(size_t)row * 16 + 8 + p] = t;
                }
            }
    }
}

// ---------------- tiny kernels ----------------
__global__ void k_dummy() {}

__global__ void k_head(const float* __restrict__ x, const float* __restrict__ wts,
                       const float* __restrict__ b3) {
    int i = blockIdx.x * 256 + threadIdx.x;
    const float* p = g_part + (size_t)i * 16;
    float4 a0 = *(const float4*)p,       a1 = *(const float4*)(p + 4);
    float4 a2 = *(const float4*)(p + 8), a3 = *(const float4*)(p + 12);
    float su = ((a0.x + a0.y) + (a0.z + a0.w)) + ((a1.x + a1.y) + (a1.z + a1.w));
    float se = ((a2.x + a2.y) + (a2.z + a2.w)) + ((a3.x + a3.y) + (a3.z + a3.w));
    float xi = x[i];
    g_r[i] = wts[i] * (se + my_sin(PI_F * xi));
    if (i == 0)         g_ub[0] = su + __ldg(b3);
    if (i == N_PTS - 1) g_ub[1] = su + __ldg(b3);
}

__global__ __launch_bounds__(256) void k_spec(const float* __restrict__ x) {
    const int kg  = blockIdx.x >> 3;
    const int seg = blockIdx.x & 7;
    const int k0  = kg * 8;
    const int i0  = seg * 4096;
    float pk[8];
#pragma unroll
    for (int q = 0; q < 8; q++) pk[q] = PI_F * (float)(k0 + 1 + q);
    float acc[8] = {0, 0, 0, 0, 0, 0, 0, 0};
    for (int i = threadIdx.x; i < 4096; i += 256) {
        float xi = x[i0 + i], ri = g_r[i0 + i];
#pragma unroll
        for (int q = 0; q < 8; q++)
            acc[q] = fmaf(my_sin(pk[q] * xi), ri, acc[q]);
    }
    __shared__ float sred[8][8];
    int lane = threadIdx.x & 31, wid = threadIdx.x >> 5;
#pragma unroll
    for (int q = 0; q < 8; q++) {
        float v = acc[q];
#pragma unroll
        for (int o = 16; o; o >>= 1) v += __shfl_down_sync(0xffffffffu, v, o);
        if (lane == 0) sred[q][wid] = v;
    }
    __syncthreads();
    if (threadIdx.x < 8) {
        float s = 0.f;
#pragma unroll
        for (int w = 0; w < 8; w++) s += sred[threadIdx.x][w];
        g_Sp[seg * KTEST + k0 + threadIdx.x] = s;
    }
}

__global__ void k_final(float* __restrict__ out) {
    __shared__ float sred[8];
    float s = 0.f;
    for (int t = threadIdx.x; t < KTEST; t += 256) {
        float v = 0.f;
#pragma unroll
        for (int seg = 0; seg < 8; seg++) v += g_Sp[seg * KTEST + t];
        s = fmaf(v, v, s);
    }
    int lane = threadIdx.x & 31, wid = threadIdx.x >> 5;
#pragma unroll
    for (int o = 16; o; o >>= 1) s += __shfl_down_sync(0xffffffffu, s, o);
    if (lane == 0) sred[wid] = s;
    __syncthreads();
    if (threadIdx.x == 0) {
        float t = 0.f;
#pragma unroll
        for (int w = 0; w < 8; w++) t += sred[w];
        out[0] = t * (1.0f / 1024.0f);
        out[1] = 5.0f * (g_ub[0] * g_ub[0] + g_ub[1] * g_ub[1]);
    }
}

extern "C" void kernel_launch(void* const* d_in, const int* in_sizes, int n_in,
                              void* d_out, int out_size) {
    const float* x   = (const float*)d_in[0];
    const float* wts = (const float*)d_in[1];
    const float* W0  = (const float*)d_in[2];
    const float* b0  = (const float*)d_in[3];
    const float* W1  = (const float*)d_in[4];
    const float* b1  = (const float*)d_in[5];
    const float* W2  = (const float*)d_in[6];
    const float* b2  = (const float*)d_in[7];
    const float* W3  = (const float*)d_in[8];
    const float* b3  = (const float*)d_in[9];

    void *pA = nullptr, *pB = nullptr;
    cudaGetSymbolAddress(&pA, g_jetA);
    cudaGetSymbolAddress(&pB, g_jetB);
    __nv_bfloat16* jA = (__nv_bfloat16*)pA;
    __nv_bfloat16* jB = (__nv_bfloat16*)pB;

    cudaFuncSetAttribute(k_layer<1>, cudaFuncAttributeMaxDynamicSharedMemorySize, SMEM_TOT);
    cudaFuncSetAttribute(k_layer<0>, cudaFuncAttributeMaxDynamicSharedMemorySize, SMEM_TOT);

    k_dummy   <<<1, 32>>>();   // shifts ncu -s window onto a layer kernel
    k_init    <<<N_PTS * 64 / 256, 256>>>(x, W0, b0);
    k_layer<1><<<512, NTHREADS, SMEM_TOT>>>(jA, jB, W1, b1, nullptr);
    k_layer<0><<<512, NTHREADS, SMEM_TOT>>>(jB, nullptr, W2, b2, W3);
    k_head    <<<N_PTS / 256, 256>>>(x, wts, b3);
    k_spec    <<<KTEST, 256>>>(x);
    k_final   <<<1, 256>>>((float*)d_out);
}

// round 11
// speedup vs baseline: 1.2524x; 1.2524x over previous
#include <cuda_runtime.h>
#include <cuda_bf16.h>
#include <cstdint>
#include <cstddef>

#define N_PTS 32768
#define HID   256
#define KTEST 1024
#define PI_F  3.14159274101257324f

// ---------------- global scratch ----------------
__device__ __nv_bfloat16 g_jetA[(size_t)N_PTS * 3 * 2 * HID];
__device__ __nv_bfloat16 g_jetB[(size_t)N_PTS * 3 * 2 * HID];
__device__ float g_part[(size_t)N_PTS * 16];
__device__ float g_r[N_PTS];
__device__ float g_Sp[8 * KTEST];
__device__ float g_ub[2];

// ---------------- math helpers ----------------
__device__ __forceinline__ float frcp(float x) {
    float r;
    asm("rcp.approx.f32 %0, %1;" : "=f"(r) : "f"(x));
    return r;
}

__device__ __forceinline__ void tanh4(const float* z, float* h) {
    float e[4], ep[4];
#pragma unroll
    for (int i = 0; i < 4; i++) {
        float zc = fminf(fmaxf(z[i], -9.0f), 9.0f);
        e[i]  = __expf(2.0f * zc);
        ep[i] = e[i] + 1.0f;
    }
    float p01   = ep[0] * ep[1];
    float p012  = p01 * ep[2];
    float p0123 = p012 * ep[3];
    float r = frcp(p0123);
    float i3 = p012 * r;  r *= ep[3];
    float i2 = p01  * r;  r *= ep[2];
    float i1 = ep[0] * r; r *= ep[1];
    float i0 = r;
    h[0] = (e[0] - 1.0f) * i0;
    h[1] = (e[1] - 1.0f) * i1;
    h[2] = (e[2] - 1.0f) * i2;
    h[3] = (e[3] - 1.0f) * i3;
}

__device__ __forceinline__ float my_sin(float a) {
    const float INV_PI = 0.3183098861837907f;
    float n = rintf(a * INV_PI);
    float r = fmaf(n, -3.14159274101257324f, a);
    r = fmaf(n, 8.742277657347586e-8f, r);
    float s2 = r * r;
    float p = -2.50521084e-8f;
    p = fmaf(p, s2, 2.75573192e-6f);
    p = fmaf(p, s2, -1.98412698e-4f);
    p = fmaf(p, s2, 8.33333333e-3f);
    p = fmaf(p, s2, -1.66666667e-1f);
    float s = fmaf(p * s2, r, r);
    return (((int)n) & 1) ? -s : s;
}

__device__ __forceinline__ void bsplit(float v, __nv_bfloat16& hi, __nv_bfloat16& lo) {
    hi = __float2bfloat16(v);
    lo = __float2bfloat16(v - __bfloat162float(hi));
}

// bf16 HMMA (sm_80+ PTX).
__device__ __forceinline__ void mma16816(float* d, const uint32_t* a, const uint32_t* b) {
    asm volatile(
        "mma.sync.aligned.m16n8k16.row.col.f32.bf16.bf16.f32 "
        "{%0,%1,%2,%3}, {%4,%5,%6,%7}, {%8,%9}, {%0,%1,%2,%3};"
        : "+f"(d[0]), "+f"(d[1]), "+f"(d[2]), "+f"(d[3])
        : "r"(a[0]), "r"(a[1]), "r"(a[2]), "r"(a[3]), "r"(b[0]), "r"(b[1]));
}

// ldmatrix x4 (sm_75+ PTX).
__device__ __forceinline__ void ldsm4(uint32_t* r, uint32_t addr) {
    asm volatile("ldmatrix.sync.aligned.m8n8.x4.shared.b16 {%0,%1,%2,%3}, [%4];"
        : "=r"(r[0]), "=r"(r[1]), "=r"(r[2]), "=r"(r[3]) : "r"(addr));
}

__device__ __forceinline__ uint32_t smem_u32(const void* p) {
    uint32_t a;
    asm("{ .reg .u64 t; cvta.to.shared.u64 t, %1; cvt.u32.u64 %0, t; }" : "=r"(a) : "l"(p));
    return a;
}

// ---------------- SMEM geometry (bf16 elements) ----------------
// B: one K=128 half at a time (restaged once): 64 rows x 136 stride, hi+lo.
#define SB_E    136
#define BHI_E   0
#define BLO_E   8704                  // 64*136
#define AB_E    17408                 // A ring start (el)
// A: un-padded SA=16 with XOR-16B swizzle; 6 tiles x 128 x 16 el per chunk.
#define TILE_E  2048                  // 128*16
#define ABUF_E  (6 * TILE_E)          // 12288 el = 24576 B per ring slot
#define NBUF    3
#define SMEM_TOT ((AB_E + NBUF * ABUF_E) * 2)   // 108544 B -> 2 CTAs/SM

// ---------------- MMA compute for one K=16 chunk (pass-major ordering) ----------------
__device__ __forceinline__ void compute_chunk(
    uint32_t smb, int abuf, int kb,
    int wm, int wn, int lane, float acc[3][2][4][4])
{
    const int t  = lane >> 3, ri = lane & 7;

    // B: one x4 per nf -> {bh0, bh1, bl0, bl1}
    uint32_t bh[4][2], bl[4][2];
#pragma unroll
    for (int nf = 0; nf < 4; nf++) {
        int n = wn * 32 + nf * 8 + ri;
        uint32_t el = ((t >> 1) ? BLO_E : BHI_E) + n * SB_E + kb + (t & 1) * 8;
        uint32_t rg[4];
        ldsm4(rg, smb + el * 2);
        bh[nf][0] = rg[0]; bh[nf][1] = rg[1];
        bl[nf][0] = rg[2]; bl[nf][1] = rg[3];
    }

    const uint32_t aBase = AB_E + abuf * ABUF_E;
    const int r  = wm * 32 + (t & 1) * 8 + ri;   // + mf*16 below
    const int s  = t >> 1;
#pragma unroll
    for (int ch = 0; ch < 3; ch++) {
        uint32_t ah[2][4], al[2][4];
#pragma unroll
        for (int mf = 0; mf < 2; mf++) {
            int rr = r + mf * 16;
            uint32_t sw = (uint32_t)((s ^ ((rr >> 2) & 1)) << 3);
            uint32_t eh = aBase + (ch * 2 + 0) * TILE_E + rr * 16 + sw;
            uint32_t el2 = aBase + (ch * 2 + 1) * TILE_E + rr * 16 + sw;
            ldsm4(ah[mf], smb + eh * 2);
            ldsm4(al[mf], smb + el2 * 2);
        }
        // pass-major: same-acc reuse distance = 8 MMAs (hides HMMA latency)
#pragma unroll
        for (int mf = 0; mf < 2; mf++)
#pragma unroll
            for (int nf = 0; nf < 4; nf++)
                mma16816(acc[ch][mf][nf], ah[mf], bh[nf]);  // pass 1: hi*hi
#pragma unroll
        for (int mf = 0; mf < 2; mf++)
#pragma unroll
            for (int nf = 0; nf < 4; nf++)
                mma16816(acc[ch][mf][nf], ah[mf], bl[nf]);  // pass 2: hi*lo
#pragma unroll
        for (int mf = 0; mf < 2; mf++)
#pragma unroll
            for (int nf = 0; nf < 4; nf++)
                mma16816(acc[ch][mf][nf], al[mf], bh[nf]);  // pass 3: lo*hi
    }
}

// cp.async prefetch of one K=16 A-chunk into ring slot c%3 (swizzled).
__device__ __forceinline__ void issue_chunk(uint32_t smb, const __nv_bfloat16* jin,
                                            int m0, int c, int tid) {
    const int kc = c * 16;
    const uint32_t dbase = smb + (uint32_t)(AB_E + (c % NBUF) * ABUF_E) * 2;
    const int r = tid >> 1, s = tid & 1;
    const uint32_t sw = (uint32_t)((s ^ ((r >> 2) & 1)) << 3);
#pragma unroll
    for (int t = 0; t < 6; t++) {
        const __nv_bfloat16* src = jin
            + (((size_t)((m0 + r) * 3 + (t >> 1)) * 2 + (t & 1)) << 8) + kc + s * 8;
        uint32_t dst = dbase + (uint32_t)(t * TILE_E + r * 16 + sw) * 2;
        unsigned long long gsrc = (unsigned long long)__cvta_generic_to_global(src);
        asm volatile("cp.async.cg.shared.global [%0], [%1], 16;" :: "r"(dst), "l"(gsrc) : "memory");
    }
    asm volatile("cp.async.commit_group;" ::: "memory");
}

// Stage one K=128 half of B = W^T (hi/lo split).
__device__ __forceinline__ void stage_B(__nv_bfloat16* sm, const float* __restrict__ W,
                                        int n0, int k0, int tid) {
#pragma unroll
    for (int it = 0; it < 8; it++) {
        int e = tid + it * 256;
        int k = e >> 4, n4 = e & 15;
        float4 v = *(const float4*)(W + (size_t)(k0 + k) * HID + n0 + n4 * 4);
        float vv[4] = {v.x, v.y, v.z, v.w};
#pragma unroll
        for (int u = 0; u < 4; u++) {
            __nv_bfloat16 hh, ll; bsplit(vv[u], hh, ll);
            int off = (n4 * 4 + u) * SB_E + k;
            sm[BHI_E + off] = hh;
            sm[BLO_E + off] = ll;
        }
    }
}

// ---------------- layer-0 jet init ----------------
__global__ __launch_bounds__(256) void k_init(const float* __restrict__ x,
                                              const float* __restrict__ W0,
                                              const float* __restrict__ b0) {
    int gid = blockIdx.x * 256 + threadIdx.x;
    int m  = gid >> 6;
    int k  = (gid & 63) << 2;
    float xm = __ldg(x + m);
    float z[4], w[4], h[4];
#pragma unroll
    for (int u = 0; u < 4; u++) {
        w[u] = __ldg(W0 + k + u);
        z[u] = fmaf(xm, w[u], __ldg(b0 + k + u));
    }
    tanh4(z, h);
    __nv_bfloat16 st[3][2][4];
#pragma unroll
    for (int u = 0; u < 4; u++) {
        float g  = fmaf(-h[u], h[u], 1.0f);
        float d  = g * w[u];
        float e2 = -2.0f * h[u] * g * w[u] * w[u];
        bsplit(h[u], st[0][0][u], st[0][1][u]);
        bsplit(d,    st[1][0][u], st[1][1][u]);
        bsplit(e2,   st[2][0][u], st[2][1][u]);
    }
#pragma unroll
    for (int ch = 0; ch < 3; ch++)
#pragma unroll
        for (int hl = 0; hl < 2; hl++)
            *(uint2*)(g_jetA + (((size_t)(m * 3 + ch) * 2 + hl) << 8) + k)
                = *(uint2*)st[ch][hl];
}

// ---------------- fused hidden layer ----------------
template<int WRITE_JET>
__global__ __launch_bounds__(256, 2) void k_layer(
    const __nv_bfloat16* __restrict__ jin, __nv_bfloat16* __restrict__ jout,
    const float* __restrict__ W, const float* __restrict__ bias,
    const float* __restrict__ W3)
{
    extern __shared__ __nv_bfloat16 sm[];
    const int tid = threadIdx.x, lane = tid & 31, wid = tid >> 5;
    const int wm = wid & 3, wn = wid >> 2;
    const int lg = lane >> 2, lq = lane & 3;
    const int nt = blockIdx.x & 3, mt = blockIdx.x >> 2;
    const int m0 = mt * 128, n0 = nt * 64;

    const uint32_t smb = smem_u32(sm);
    issue_chunk(smb, jin, m0, 0, tid);
    issue_chunk(smb, jin, m0, 1, tid);
    stage_B(sm, W, n0, 0, tid);

    float acc[3][2][4][4];
#pragma unroll
    for (int ch = 0; ch < 3; ch++)
#pragma unroll
        for (int mf = 0; mf < 2; mf++)
#pragma unroll
            for (int nf = 0; nf < 4; nf++)
#pragma unroll
                for (int rr = 0; rr < 4; rr++) acc[ch][mf][nf][rr] = 0.f;

    // ---- 16 chunks of K=16, 3-deep cp.async ring, 1 barrier/chunk ----
    for (int c = 0; c < 16; c++) {
        if (c < 15) { asm volatile("cp.async.wait_group 1;" ::: "memory"); }
        else        { asm volatile("cp.async.wait_group 0;" ::: "memory"); }
        __syncthreads();   // all warps: chunk c data visible, compute c-1 done
        if (c == 8) {      // swap B to K half [128,256)
            stage_B(sm, W, n0, 128, tid);
            __syncthreads();
        }
        if (c + 2 < 16) issue_chunk(smb, jin, m0, c + 2, tid);
        compute_chunk(smb, c % NBUF, (c & 7) * 16, wm, wn, lane, acc);
    }

    // ---- epilogue ----
    if (WRITE_JET) {
#pragma unroll
        for (int mf = 0; mf < 2; mf++)
#pragma unroll
            for (int rh = 0; rh < 2; rh++) {
                const int row = m0 + wm * 32 + mf * 16 + rh * 8 + lg;
                float zz[8], aa[8], cc[8], hh[8];
#pragma unroll
                for (int nf = 0; nf < 4; nf++)
#pragma unroll
                    for (int u = 0; u < 2; u++) {
                        const int e = nf * 2 + u;
                        const int col = n0 + wn * 32 + nf * 8 + lq * 2 + u;
                        zz[e] = acc[0][mf][nf][rh * 2 + u] + __ldg(bias + col);
                        aa[e] = acc[1][mf][nf][rh * 2 + u];
                        cc[e] = acc[2][mf][nf][rh * 2 + u];
                    }
                tanh4(zz, hh);
                tanh4(zz + 4, hh + 4);
#pragma unroll
                for (int nf = 0; nf < 4; nf++) {
                    const int col = n0 + wn * 32 + nf * 8 + lq * 2;
                    const int e0 = nf * 2, e1 = nf * 2 + 1;
                    float h0 = hh[e0], h1 = hh[e1];
                    float g0 = fmaf(-h0, h0, 1.0f), g1 = fmaf(-h1, h1, 1.0f);
                    float d0 = g0 * aa[e0], d1 = g1 * aa[e1];
                    float ev0 = g0 * fmaf(-2.0f * h0 * aa[e0], aa[e0], cc[e0]);
                    float ev1 = g1 * fmaf(-2.0f * h1 * aa[e1], aa[e1], cc[e1]);
                    float vs[3][2] = {{h0, h1}, {d0, d1}, {ev0, ev1}};
#pragma unroll
                    for (int ch = 0; ch < 3; ch++) {
                        __nv_bfloat16 hA, lA, hB, lB;
                        bsplit(vs[ch][0], hA, lA);
                        bsplit(vs[ch][1], hB, lB);
                        __nv_bfloat162 hp = __halves2bfloat162(hA, hB);
                        __nv_bfloat162 lp = __halves2bfloat162(lA, lB);
                        *(uint32_t*)(jout + (((size_t)(row * 3 + ch) * 2 + 0) << 8) + col) = *(uint32_t*)&hp;
                        *(uint32_t*)(jout + (((size_t)(row * 3 + ch) * 2 + 1) << 8) + col) = *(uint32_t*)&lp;
                    }
                }
            }
    } else {
        float su[2][2] = {{0.f, 0.f}, {0.f, 0.f}};
        float se[2][2] = {{0.f, 0.f}, {0.f, 0.f}};
#pragma unroll
        for (int mf = 0; mf < 2; mf++)
#pragma unroll
            for (int rh = 0; rh < 2; rh++) {
                float zz[8], aa[8], cc[8], hh[8];
#pragma unroll
                for (int nf = 0; nf < 4; nf++)
#pragma unroll
                    for (int u = 0; u < 2; u++) {
                        const int e = nf * 2 + u;
                        const int col = n0 + wn * 32 + nf * 8 + lq * 2 + u;
                        zz[e] = acc[0][mf][nf][rh * 2 + u] + __ldg(bias + col);
                        aa[e] = acc[1][mf][nf][rh * 2 + u];
                        cc[e] = acc[2][mf][nf][rh * 2 + u];
                    }
                tanh4(zz, hh);
                tanh4(zz + 4, hh + 4);
#pragma unroll
                for (int nf = 0; nf < 4; nf++) {
                    const int col = n0 + wn * 32 + nf * 8 + lq * 2;
                    const int e0 = nf * 2, e1 = nf * 2 + 1;
                    float h0 = hh[e0], h1 = hh[e1];
                    float g0 = fmaf(-h0, h0, 1.0f), g1 = fmaf(-h1, h1, 1.0f);
                    float ev0 = g0 * fmaf(-2.0f * h0 * aa[e0], aa[e0], cc[e0]);
                    float ev1 = g1 * fmaf(-2.0f * h1 * aa[e1], aa[e1], cc[e1]);
                    float w30 = __ldg(W3 + col), w31 = __ldg(W3 + col + 1);
                    su[mf][rh] = fmaf(h0, w30, fmaf(h1, w31, su[mf][rh]));
                    se[mf][rh] = fmaf(ev0, w30, fmaf(ev1, w31, se[mf][rh]));
                }
            }
#pragma unroll
        for (int mf = 0; mf < 2; mf++)
#pragma unroll
            for (int rh = 0; rh < 2; rh++) {
                float s = su[mf][rh];
                s += __shfl_xor_sync(0xffffffffu, s, 1);
                s += __shfl_xor_sync(0xffffffffu, s, 2);
                float t = se[mf][rh];
                t += __shfl_xor_sync(0xffffffffu, t, 1);
                t += __shfl_xor_sync(0xffffffffu, t, 2);
                if (lq == 0) {
                    const int row = m0 + wm * 32 + mf * 16 + rh * 8 + lg;
                    const int p = nt * 2 + wn;
                    g_part[(size_t)row * 16 + p]     = s;
                    g_part[(size_t)row * 16 + 8 + p] = t;
                }
            }
    }
}

// ---------------- tiny kernels ----------------
__global__ void k_dummy() {}

__global__ void k_head(const float* __restrict__ x, const float* __restrict__ wts,
                       const float* __restrict__ b3) {
    int i = blockIdx.x * 256 + threadIdx.x;
    const float* p = g_part + (size_t)i * 16;
    float4 a0 = *(const float4*)p,       a1 = *(const float4*)(p + 4);
    float4 a2 = *(const float4*)(p + 8), a3 = *(const float4*)(p + 12);
    float su = ((a0.x + a0.y) + (a0.z + a0.w)) + ((a1.x + a1.y) + (a1.z + a1.w));
    float se = ((a2.x + a2.y) + (a2.z + a2.w)) + ((a3.x + a3.y) + (a3.z + a3.w));
    float xi = x[i];
    g_r[i] = wts[i] * (se + my_sin(PI_F * xi));
    if (i == 0)         g_ub[0] = su + __ldg(b3);
    if (i == N_PTS - 1) g_ub[1] = su + __ldg(b3);
}

__global__ __launch_bounds__(256) void k_spec(const float* __restrict__ x) {
    const int kg  = blockIdx.x >> 3;
    const int seg = blockIdx.x & 7;
    const int k0  = kg * 8;
    const int i0  = seg * 4096;
    float pk[8];
#pragma unroll
    for (int q = 0; q < 8; q++) pk[q] = PI_F * (float)(k0 + 1 + q);
    float acc[8] = {0, 0, 0, 0, 0, 0, 0, 0};
    for (int i = threadIdx.x; i < 4096; i += 256) {
        float xi = x[i0 + i], ri = g_r[i0 + i];
#pragma unroll
        for (int q = 0; q < 8; q++)
            acc[q] = fmaf(my_sin(pk[q] * xi), ri, acc[q]);
    }
    __shared__ float sred[8][8];
    int lane = threadIdx.x & 31, wid = threadIdx.x >> 5;
#pragma unroll
    for (int q = 0; q < 8; q++) {
        float v = acc[q];
#pragma unroll
        for (int o = 16; o; o >>= 1) v += __shfl_down_sync(0xffffffffu, v, o);
        if (lane == 0) sred[q][wid] = v;
    }
    __syncthreads();
    if (threadIdx.x < 8) {
        float s = 0.f;
#pragma unroll
        for (int w = 0; w < 8; w++) s += sred[threadIdx.x][w];
        g_Sp[seg * KTEST + k0 + threadIdx.x] = s;
    }
}

__global__ void k_final(float* __restrict__ out) {
    __shared__ float sred[8];
    float s = 0.f;
    for (int t = threadIdx.x; t < KTEST; t += 256) {
        float v = 0.f;
#pragma unroll
        for (int seg = 0; seg < 8; seg++) v += g_Sp[seg * KTEST + t];
        s = fmaf(v, v, s);
    }
    int lane = threadIdx.x & 31, wid = threadIdx.x >> 5;
#pragma unroll
    for (int o = 16; o; o >>= 1) s += __shfl_down_sync(0xffffffffu, s, o);
    if (lane == 0) sred[wid] = s;
    __syncthreads();
    if (threadIdx.x == 0) {
        float t = 0.f;
#pragma unroll
        for (int w = 0; w < 8; w++) t += sred[w];
        out[0] = t * (1.0f / 1024.0f);
        out[1] = 5.0f * (g_ub[0] * g_ub[0] + g_ub[1] * g_ub[1]);
    }
}

extern "C" void kernel_launch(void* const* d_in, const int* in_sizes, int n_in,
                              void* d_out, int out_size) {
    const float* x   = (const float*)d_in[0];
    const float* wts = (const float*)d_in[1];
    const float* W0  = (const float*)d_in[2];
    const float* b0  = (const float*)d_in[3];
    const float* W1  = (const float*)d_in[4];
    const float* b1  = (const float*)d_in[5];
    const float* W2  = (const float*)d_in[6];
    const float* b2  = (const float*)d_in[7];
    const float* W3  = (const float*)d_in[8];
    const float* b3  = (const float*)d_in[9];

    void *pA = nullptr, *pB = nullptr;
    cudaGetSymbolAddress(&pA, g_jetA);
    cudaGetSymbolAddress(&pB, g_jetB);
    __nv_bfloat16* jA = (__nv_bfloat16*)pA;
    __nv_bfloat16* jB = (__nv_bfloat16*)pB;

    cudaFuncSetAttribute(k_layer<1>, cudaFuncAttributeMaxDynamicSharedMemorySize, SMEM_TOT);
    cudaFuncSetAttribute(k_layer<0>, cudaFuncAttributeMaxDynamicSharedMemorySize, SMEM_TOT);

    k_dummy   <<<1, 32>>>();   // shifts ncu -s window onto a layer kernel
    k_init    <<<N_PTS * 64 / 256, 256>>>(x, W0, b0);
    k_layer<1><<<1024, 256, SMEM_TOT>>>(jA, jB, W1, b1, nullptr);
    k_layer<0><<<1024, 256, SMEM_TOT>>>(jB, nullptr, W2, b2, W3);
    k_head    <<<N_PTS / 256, 256>>>(x, wts, b3);
    k_spec    <<<KTEST, 256>>>(x);
    k_final   <<<1, 256>>>((float*)d_out);
}